// round 10
// baseline (speedup 1.0000x reference)
#include <cuda_runtime.h>
#include <cuda_fp16.h>

#define N0C 100000
#define N1C 100000

#define KV_BLOCKS ((N0C + 127) / 128)   // 782
#define Q_BLOCKS  ((N1C + 127) / 128)   // 782

// KV0 in fp16, padded rows of 128 halves (256B, line-aligned):
//   halves [0,32)   : K part   halves [64,128) : V part
__device__ __half g_KVh[(size_t)N0C * 128];
__device__ float  g_Q[(size_t)N1C * 32];

// Precomputed mma B-fragments (weights), hi/lo split.
// KV: e = ((k*12 + n)*2 + s)*32 + lane; regs at [2e, 2e+1].
__device__ unsigned g_fragB_kv[5 * 12 * 2 * 32 * 2];
// Q:  e = ((k*4 + n)*2 + s)*32 + lane.
__device__ unsigned g_fragB_q[4 * 4 * 2 * 32 * 2];

#define MMA16816(D, A0, A1, A2, A3, B0, B1)                                  \
    asm volatile(                                                            \
        "mma.sync.aligned.m16n8k16.row.col.f32.f16.f16.f32 "                 \
        "{%0,%1,%2,%3},{%4,%5,%6,%7},{%8,%9},{%0,%1,%2,%3};"                 \
        : "+f"(D[0]), "+f"(D[1]), "+f"(D[2]), "+f"(D[3])                     \
        : "r"(A0), "r"(A1), "r"(A2), "r"(A3), "r"(B0), "r"(B1))

__device__ __forceinline__ __half wsplit(float w, int s) {
    __half h = __float2half_rn(w);
    if (s) h = __float2half_rn(w - __half2float(h));
    return h;
}
__device__ __forceinline__ unsigned packh2(__half a, __half b) {
    __half2 p = __halves2half2(a, b);
    return *(unsigned*)&p;
}

// ---------------------------------------------------------------------------
// Kernel 0: build B-fragment tables (one small block).
// Combined KV weight matrix Wc[80][96]: rows 0..66 = [Wk | Wv], rows 67..79 = 0.
// ---------------------------------------------------------------------------
__global__ __launch_bounds__(512) void prepw_kernel(
    const float* __restrict__ Wk, const float* __restrict__ Wv,
    const float* __restrict__ Wq)
{
    const int t = threadIdx.x;

    for (int e = t; e < 5 * 12 * 2 * 32; e += 512) {
        int l = e & 31, s = (e >> 5) & 1;
        int nk = e >> 6;
        int n = nk % 12, k = nk / 12;
        int c = n * 8 + (l >> 2);
        int kb = k * 16 + 2 * (l & 3);
#pragma unroll
        for (int half_ = 0; half_ < 2; half_++) {
            int r0 = kb + half_ * 8;
            float w0 = 0.f, w1 = 0.f;
            if (r0 < 67)     w0 = (c < 32) ? Wk[r0 * 32 + c] : Wv[r0 * 64 + (c - 32)];
            if (r0 + 1 < 67) w1 = (c < 32) ? Wk[(r0 + 1) * 32 + c] : Wv[(r0 + 1) * 64 + (c - 32)];
            g_fragB_kv[2 * e + half_] = packh2(wsplit(w0, s), wsplit(w1, s));
        }
    }

    for (int e = t; e < 4 * 4 * 2 * 32; e += 512) {
        int l = e & 31, s = (e >> 5) & 1;
        int nk = e >> 6;
        int n = nk % 4, k = nk / 4;
        int c = n * 8 + (l >> 2);
        int kb = k * 16 + 2 * (l & 3);
#pragma unroll
        for (int half_ = 0; half_ < 2; half_++) {
            int r0 = kb + half_ * 8;
            float w0 = Wq[r0 * 32 + c];
            float w1 = Wq[(r0 + 1) * 32 + c];
            g_fragB_q[2 * e + half_] = packh2(wsplit(w0, s), wsplit(w1, s));
        }
    }
}

// ---------------------------------------------------------------------------
// Kernel 1: fused tensor-core prep. Blocks [0,782) KV GEMM, [782,1564) Q GEMM,
// rest idx-copy. 512 threads; 128-row tiles; warp = 16 rows x (48|16) cols.
// ---------------------------------------------------------------------------
__global__ __launch_bounds__(512) void prep_kernel(
    const float* __restrict__ feats0, const float* __restrict__ coords0,
    const float* __restrict__ bk, const float* __restrict__ bv,
    const float* __restrict__ feats1, const float* __restrict__ bq,
    const int* __restrict__ knn, float* __restrict__ outTail, int tailN)
{
    __shared__ __align__(16) unsigned char sbuf[45056];
    const int t = threadIdx.x;

    if (blockIdx.x < KV_BLOCKS) {
        // ------------- KV0: [128 rows, 80k(pad)] x [80, 96] -------------
        __half (*Xhi)[88] = (__half(*)[88])sbuf;
        __half (*Xlo)[88] = (__half(*)[88])(sbuf + 128 * 88 * 2);

        const int base = blockIdx.x * 128;
        for (int idx = t; idx < 128 * 80; idx += 512) {
            int r = idx / 80, kc = idx % 80;
            int pt = base + r;
            float v = 0.f;
            if (pt < N0C && kc < 67)
                v = (kc < 64) ? feats0[(size_t)pt * 64 + kc]
                              : coords0[(size_t)pt * 3 + (kc - 64)];
            __half h = __float2half_rn(v);
            Xhi[r][kc] = h;
            Xlo[r][kc] = __float2half_rn(v - __half2float(h));
        }
        __syncthreads();

        const int w = t >> 5, l = t & 31;
        const int wr = (w >> 1) * 16;       // warp's row base
        const int jb = (w & 1) * 6;         // warp's ntile base (6 tiles of 8)
        const int gr = l >> 2, c0 = 2 * (l & 3);

        float D[6][4];
#pragma unroll
        for (int j = 0; j < 6; j++) {
            int colg = (jb + j) * 8 + c0;
            float2 bb = (colg < 32) ? *(const float2*)(bk + colg)
                                    : *(const float2*)(bv + (colg - 32));
            D[j][0] = bb.x; D[j][1] = bb.y; D[j][2] = bb.x; D[j][3] = bb.y;
        }

#pragma unroll
        for (int k = 0; k < 5; k++) {
            const int ka = k * 16 + c0;
            unsigned ah0 = *(const unsigned*)&Xhi[wr + gr][ka];
            unsigned ah1 = *(const unsigned*)&Xhi[wr + gr + 8][ka];
            unsigned ah2 = *(const unsigned*)&Xhi[wr + gr][ka + 8];
            unsigned ah3 = *(const unsigned*)&Xhi[wr + gr + 8][ka + 8];
            unsigned al0 = *(const unsigned*)&Xlo[wr + gr][ka];
            unsigned al1 = *(const unsigned*)&Xlo[wr + gr + 8][ka];
            unsigned al2 = *(const unsigned*)&Xlo[wr + gr][ka + 8];
            unsigned al3 = *(const unsigned*)&Xlo[wr + gr + 8][ka + 8];
#pragma unroll
            for (int j = 0; j < 6; j++) {
                int n = jb + j;
                const uint2 bh = *(const uint2*)&g_fragB_kv[((k * 12 + n) * 2 + 0) * 64 + l * 2];
                const uint2 bl = *(const uint2*)&g_fragB_kv[((k * 12 + n) * 2 + 1) * 64 + l * 2];
                MMA16816(D[j], ah0, ah1, ah2, ah3, bh.x, bh.y);
                MMA16816(D[j], ah0, ah1, ah2, ah3, bl.x, bl.y);
                MMA16816(D[j], al0, al1, al2, al3, bh.x, bh.y);
            }
        }

        const int r0 = base + wr + gr;
        const int r1 = r0 + 8;
#pragma unroll
        for (int j = 0; j < 6; j++) {
            int colg = (jb + j) * 8 + c0;
            int hidx = (colg < 32) ? colg : colg + 32;
            if (r0 < N0C)
                *(__half2*)(g_KVh + (size_t)r0 * 128 + hidx) = __floats2half2_rn(D[j][0], D[j][1]);
            if (r1 < N0C)
                *(__half2*)(g_KVh + (size_t)r1 * 128 + hidx) = __floats2half2_rn(D[j][2], D[j][3]);
        }
    } else if (blockIdx.x < KV_BLOCKS + Q_BLOCKS) {
        // ------------- Q: [128 rows, 64k] x [64, 32] -------------
        __half (*Xhi)[72] = (__half(*)[72])sbuf;
        __half (*Xlo)[72] = (__half(*)[72])(sbuf + 128 * 72 * 2);

        const int base = (blockIdx.x - KV_BLOCKS) * 128;
        for (int idx = t; idx < 128 * 64; idx += 512) {
            int r = idx >> 6, kc = idx & 63;
            int pt = base + r;
            float v = (pt < N1C) ? feats1[(size_t)pt * 64 + kc] : 0.f;
            __half h = __float2half_rn(v);
            Xhi[r][kc] = h;
            Xlo[r][kc] = __float2half_rn(v - __half2float(h));
        }
        __syncthreads();

        const int w = t >> 5, l = t & 31;
        const int wr = (w >> 1) * 16;
        const int jb = (w & 1) * 2;         // 2 ntiles of 8 cols
        const int gr = l >> 2, c0 = 2 * (l & 3);

        float D[2][4];
#pragma unroll
        for (int j = 0; j < 2; j++) {
            float2 bb = *(const float2*)(bq + (jb + j) * 8 + c0);
            D[j][0] = bb.x; D[j][1] = bb.y; D[j][2] = bb.x; D[j][3] = bb.y;
        }

#pragma unroll
        for (int k = 0; k < 4; k++) {
            const int ka = k * 16 + c0;
            unsigned ah0 = *(const unsigned*)&Xhi[wr + gr][ka];
            unsigned ah1 = *(const unsigned*)&Xhi[wr + gr + 8][ka];
            unsigned ah2 = *(const unsigned*)&Xhi[wr + gr][ka + 8];
            unsigned ah3 = *(const unsigned*)&Xhi[wr + gr + 8][ka + 8];
            unsigned al0 = *(const unsigned*)&Xlo[wr + gr][ka];
            unsigned al1 = *(const unsigned*)&Xlo[wr + gr + 8][ka];
            unsigned al2 = *(const unsigned*)&Xlo[wr + gr][ka + 8];
            unsigned al3 = *(const unsigned*)&Xlo[wr + gr + 8][ka + 8];
#pragma unroll
            for (int j = 0; j < 2; j++) {
                int n = jb + j;
                const uint2 bh = *(const uint2*)&g_fragB_q[((k * 4 + n) * 2 + 0) * 64 + l * 2];
                const uint2 bl = *(const uint2*)&g_fragB_q[((k * 4 + n) * 2 + 1) * 64 + l * 2];
                MMA16816(D[j], ah0, ah1, ah2, ah3, bh.x, bh.y);
                MMA16816(D[j], ah0, ah1, ah2, ah3, bl.x, bl.y);
                MMA16816(D[j], al0, al1, al2, al3, bh.x, bh.y);
            }
        }

        const int r0 = base + wr + gr;
        const int r1 = r0 + 8;
#pragma unroll
        for (int j = 0; j < 2; j++) {
            int colg = (jb + j) * 8 + c0;
            if (r0 < N1C)
                *(float2*)(g_Q + (size_t)r0 * 32 + colg) = make_float2(D[j][0], D[j][1]);
            if (r1 < N1C)
                *(float2*)(g_Q + (size_t)r1 * 32 + colg) = make_float2(D[j][2], D[j][3]);
        }
    } else {
        // ------------- knn_idxs passthrough (int -> float) -------------
        int b = blockIdx.x - KV_BLOCKS - Q_BLOCKS;
        int stride = (gridDim.x - KV_BLOCKS - Q_BLOCKS) * 512;
        for (int i = b * 512 + t; i < tailN; i += stride)
            outTail[i] = (float)knn[i];
    }
}

// ---------------------------------------------------------------------------
// Attention: one warp per query, 8 queries per 256-thread block. (Unchanged.)
// ---------------------------------------------------------------------------
__global__ __launch_bounds__(256) void attn_kernel(
    const float* __restrict__ coords1,
    const int*   __restrict__ knn,
    const float* __restrict__ Wv,
    float*       __restrict__ out)
{
    const int l = threadIdx.x & 31;
    const int n = blockIdx.x * 8 + (threadIdx.x >> 5);

    int myidx = 0;
    if (l < 16) myidx = knn[(size_t)n * 16 + l];

    const int h    = l & 3;
    const int rsub = l >> 2;

    const float4 q0 = *(const float4*)(g_Q + (size_t)n * 32 + h * 8);
    const float4 q1 = *(const float4*)(g_Q + (size_t)n * 32 + h * 8 + 4);

    const int j0 = __shfl_sync(0xffffffffu, myidx, rsub);
    const int j1 = __shfl_sync(0xffffffffu, myidx, 8 + rsub);

    const uint4 kc0 = *(const uint4*)(g_KVh + (size_t)j0 * 128 + h * 8);
    const uint4 kc1 = *(const uint4*)(g_KVh + (size_t)j1 * 128 + h * 8);

    float logit0, logit1;
    {
        const __half2* kh = (const __half2*)&kc0;
        float2 a = __half22float2(kh[0]), b = __half22float2(kh[1]);
        float2 c = __half22float2(kh[2]), d = __half22float2(kh[3]);
        logit0 = a.x * q0.x + a.y * q0.y + b.x * q0.z + b.y * q0.w
               + c.x * q1.x + c.y * q1.y + d.x * q1.z + d.y * q1.w;
    }
    {
        const __half2* kh = (const __half2*)&kc1;
        float2 a = __half22float2(kh[0]), b = __half22float2(kh[1]);
        float2 c = __half22float2(kh[2]), d = __half22float2(kh[3]);
        logit1 = a.x * q0.x + a.y * q0.y + b.x * q0.z + b.y * q0.w
               + c.x * q1.x + c.y * q1.y + d.x * q1.z + d.y * q1.w;
    }
    logit0 *= 0.35355339059327373f;
    logit1 *= 0.35355339059327373f;

    float m = fmaxf(logit0, logit1);
    m = fmaxf(m, __shfl_xor_sync(0xffffffffu, m, 4));
    m = fmaxf(m, __shfl_xor_sync(0xffffffffu, m, 8));
    m = fmaxf(m, __shfl_xor_sync(0xffffffffu, m, 16));
    float e0 = __expf(logit0 - m);
    float e1 = __expf(logit1 - m);
    float s = e0 + e1;
    s += __shfl_xor_sync(0xffffffffu, s, 4);
    s += __shfl_xor_sync(0xffffffffu, s, 8);
    s += __shfl_xor_sync(0xffffffffu, s, 16);
    const float inv_s = __frcp_rn(s);
    const float a0 = e0 * inv_s;
    const float a1 = e1 * inv_s;

    const int hd = l >> 3;
    float accx = 0.0f, accy = 0.0f;
#pragma unroll
    for (int r = 0; r < 16; r++) {
        const int jr = __shfl_sync(0xffffffffu, myidx, r);
        const int src = ((r & 7) << 2) + hd;
        const float ar = __shfl_sync(0xffffffffu, (r < 8) ? a0 : a1, src);
        const __half2 v = *(const __half2*)(g_KVh + (size_t)jr * 128 + 64 + 2 * l);
        const float2 vf = __half22float2(v);
        accx = fmaf(ar, vf.x, accx);
        accy = fmaf(ar, vf.y, accy);
    }

    const float c1x = coords1[(size_t)n * 3 + 0];
    const float c1y = coords1[(size_t)n * 3 + 1];
    const float c1z = coords1[(size_t)n * 3 + 2];
    const float2 wv0 = *(const float2*)(Wv + (size_t)64 * 64 + 2 * l);
    const float2 wv1 = *(const float2*)(Wv + (size_t)65 * 64 + 2 * l);
    const float2 wv2 = *(const float2*)(Wv + (size_t)66 * 64 + 2 * l);
    const float cvx = c1x * wv0.x + c1y * wv1.x + c1z * wv2.x;
    const float cvy = c1x * wv0.y + c1y * wv1.y + c1z * wv2.y;

    *(float2*)(out + (size_t)n * 64 + 2 * l) = make_float2(accx - cvx, accy - cvy);
}

extern "C" void kernel_launch(void* const* d_in, const int* in_sizes, int n_in,
                              void* d_out, int out_size)
{
    const float* coords0 = (const float*)d_in[0];
    const float* coords1 = (const float*)d_in[1];
    const float* feats0  = (const float*)d_in[2];
    const float* feats1  = (const float*)d_in[3];
    const int*   knn     = (const int*)  d_in[4];
    const float* Wq      = (const float*)d_in[5];
    const float* bq      = (const float*)d_in[6];
    const float* Wk      = (const float*)d_in[7];
    const float* bk      = (const float*)d_in[8];
    const float* Wv      = (const float*)d_in[9];
    const float* bv      = (const float*)d_in[10];
    float* out = (float*)d_out;

    int tail = out_size - N1C * 64;
    if (tail < 0) tail = 0;
    int copyBlocks = tail > 0 ? (tail + 2047) / 2048 : 0;

    prepw_kernel<<<1, 512>>>(Wk, Wv, Wq);

    prep_kernel<<<KV_BLOCKS + Q_BLOCKS + copyBlocks, 512>>>(
        feats0, coords0, bk, bv, feats1, bq,
        knn, out + (size_t)N1C * 64, tail);

    attn_kernel<<<N1C / 8, 256>>>(coords1, knn, Wv, out);
}

// round 11
// speedup vs baseline: 1.3644x; 1.3644x over previous
#include <cuda_runtime.h>
#include <cuda_fp16.h>

#define N0C 100000
#define N1C 100000

#define KV_BLOCKS ((N0C + 127) / 128)   // 782
#define Q_BLOCKS  ((N1C + 127) / 128)   // 782

// KV0 in fp16, padded rows of 128 halves (256B, line-aligned):
//   halves [0,32)   : K part   halves [64,128) : V part
__device__ __half g_KVh[(size_t)N0C * 128];
__device__ float  g_Q[(size_t)N1C * 32];

// Precomputed mma B-fragments (weights), hi/lo split.
// KV: e = ((k*12 + n)*2 + s)*32 + lane; regs at [2e, 2e+1].
__device__ unsigned g_fragB_kv[5 * 12 * 2 * 32 * 2];
// Q:  e = ((k*4 + n)*2 + s)*32 + lane.
__device__ unsigned g_fragB_q[4 * 4 * 2 * 32 * 2];

#define MMA16816(D, A0, A1, A2, A3, B0, B1)                                  \
    asm volatile(                                                            \
        "mma.sync.aligned.m16n8k16.row.col.f32.f16.f16.f32 "                 \
        "{%0,%1,%2,%3},{%4,%5,%6,%7},{%8,%9},{%0,%1,%2,%3};"                 \
        : "+f"(D[0]), "+f"(D[1]), "+f"(D[2]), "+f"(D[3])                     \
        : "r"(A0), "r"(A1), "r"(A2), "r"(A3), "r"(B0), "r"(B1))

__device__ __forceinline__ __half wsplit(float w, int s) {
    __half h = __float2half_rn(w);
    if (s) h = __float2half_rn(w - __half2float(h));
    return h;
}
__device__ __forceinline__ unsigned packh2(__half a, __half b) {
    __half2 p = __halves2half2(a, b);
    return *(unsigned*)&p;
}

// ---------------------------------------------------------------------------
// Kernel 0: build B-fragment tables (one small block).
// Combined KV weight matrix Wc[80][96]: rows 0..66 = [Wk | Wv], rows 67..79 = 0.
// ---------------------------------------------------------------------------
__global__ __launch_bounds__(512) void prepw_kernel(
    const float* __restrict__ Wk, const float* __restrict__ Wv,
    const float* __restrict__ Wq)
{
    const int t = threadIdx.x;

    for (int e = t; e < 5 * 12 * 2 * 32; e += 512) {
        int l = e & 31, s = (e >> 5) & 1;
        int nk = e >> 6;
        int n = nk % 12, k = nk / 12;
        int c = n * 8 + (l >> 2);
        int kb = k * 16 + 2 * (l & 3);
#pragma unroll
        for (int half_ = 0; half_ < 2; half_++) {
            int r0 = kb + half_ * 8;
            float w0 = 0.f, w1 = 0.f;
            if (r0 < 67)     w0 = (c < 32) ? Wk[r0 * 32 + c] : Wv[r0 * 64 + (c - 32)];
            if (r0 + 1 < 67) w1 = (c < 32) ? Wk[(r0 + 1) * 32 + c] : Wv[(r0 + 1) * 64 + (c - 32)];
            g_fragB_kv[2 * e + half_] = packh2(wsplit(w0, s), wsplit(w1, s));
        }
    }

    for (int e = t; e < 4 * 4 * 2 * 32; e += 512) {
        int l = e & 31, s = (e >> 5) & 1;
        int nk = e >> 6;
        int n = nk % 4, k = nk / 4;
        int c = n * 8 + (l >> 2);
        int kb = k * 16 + 2 * (l & 3);
#pragma unroll
        for (int half_ = 0; half_ < 2; half_++) {
            int r0 = kb + half_ * 8;
            float w0 = Wq[r0 * 32 + c];
            float w1 = Wq[(r0 + 1) * 32 + c];
            g_fragB_q[2 * e + half_] = packh2(wsplit(w0, s), wsplit(w1, s));
        }
    }
}

// ---------------------------------------------------------------------------
// Kernel 1: fused tensor-core prep. Blocks [0,782) KV GEMM, [782,1564) Q GEMM,
// rest idx-copy. 512 threads; 128-row tiles; warp = 16 rows x (48|16) cols.
// ---------------------------------------------------------------------------
__global__ __launch_bounds__(512) void prep_kernel(
    const float* __restrict__ feats0, const float* __restrict__ coords0,
    const float* __restrict__ bk, const float* __restrict__ bv,
    const float* __restrict__ feats1, const float* __restrict__ bq,
    const int* __restrict__ knn, float* __restrict__ outTail, int tailN)
{
    __shared__ __align__(16) unsigned char sbuf[45056];
    const int t = threadIdx.x;

    if (blockIdx.x < KV_BLOCKS) {
        // ------------- KV0: [128 rows, 80k(pad)] x [80, 96] -------------
        __half (*Xhi)[88] = (__half(*)[88])sbuf;
        __half (*Xlo)[88] = (__half(*)[88])(sbuf + 128 * 88 * 2);

        const int base = blockIdx.x * 128;
        for (int idx = t; idx < 128 * 80; idx += 512) {
            int r = idx / 80, kc = idx % 80;
            int pt = base + r;
            float v = 0.f;
            if (pt < N0C && kc < 67)
                v = (kc < 64) ? feats0[(size_t)pt * 64 + kc]
                              : coords0[(size_t)pt * 3 + (kc - 64)];
            __half h = __float2half_rn(v);
            Xhi[r][kc] = h;
            Xlo[r][kc] = __float2half_rn(v - __half2float(h));
        }
        __syncthreads();

        const int w = t >> 5, l = t & 31;
        const int wr = (w >> 1) * 16;       // warp's row base
        const int jb = (w & 1) * 6;         // warp's ntile base (6 tiles of 8)
        const int gr = l >> 2, c0 = 2 * (l & 3);

        float D[6][4];
#pragma unroll
        for (int j = 0; j < 6; j++) {
            int colg = (jb + j) * 8 + c0;
            float2 bb = (colg < 32) ? *(const float2*)(bk + colg)
                                    : *(const float2*)(bv + (colg - 32));
            D[j][0] = bb.x; D[j][1] = bb.y; D[j][2] = bb.x; D[j][3] = bb.y;
        }

#pragma unroll
        for (int k = 0; k < 5; k++) {
            const int ka = k * 16 + c0;
            unsigned ah0 = *(const unsigned*)&Xhi[wr + gr][ka];
            unsigned ah1 = *(const unsigned*)&Xhi[wr + gr + 8][ka];
            unsigned ah2 = *(const unsigned*)&Xhi[wr + gr][ka + 8];
            unsigned ah3 = *(const unsigned*)&Xhi[wr + gr + 8][ka + 8];
            unsigned al0 = *(const unsigned*)&Xlo[wr + gr][ka];
            unsigned al1 = *(const unsigned*)&Xlo[wr + gr + 8][ka];
            unsigned al2 = *(const unsigned*)&Xlo[wr + gr][ka + 8];
            unsigned al3 = *(const unsigned*)&Xlo[wr + gr + 8][ka + 8];
#pragma unroll
            for (int j = 0; j < 6; j++) {
                int n = jb + j;
                const uint2 bh = *(const uint2*)&g_fragB_kv[((k * 12 + n) * 2 + 0) * 64 + l * 2];
                const uint2 bl = *(const uint2*)&g_fragB_kv[((k * 12 + n) * 2 + 1) * 64 + l * 2];
                MMA16816(D[j], ah0, ah1, ah2, ah3, bh.x, bh.y);
                MMA16816(D[j], ah0, ah1, ah2, ah3, bl.x, bl.y);
                MMA16816(D[j], al0, al1, al2, al3, bh.x, bh.y);
            }
        }

        const int r0 = base + wr + gr;
        const int r1 = r0 + 8;
#pragma unroll
        for (int j = 0; j < 6; j++) {
            int colg = (jb + j) * 8 + c0;
            int hidx = (colg < 32) ? colg : colg + 32;
            if (r0 < N0C)
                *(__half2*)(g_KVh + (size_t)r0 * 128 + hidx) = __floats2half2_rn(D[j][0], D[j][1]);
            if (r1 < N0C)
                *(__half2*)(g_KVh + (size_t)r1 * 128 + hidx) = __floats2half2_rn(D[j][2], D[j][3]);
        }
    } else if (blockIdx.x < KV_BLOCKS + Q_BLOCKS) {
        // ------------- Q: [128 rows, 64k] x [64, 32] -------------
        __half (*Xhi)[72] = (__half(*)[72])sbuf;
        __half (*Xlo)[72] = (__half(*)[72])(sbuf + 128 * 72 * 2);

        const int base = (blockIdx.x - KV_BLOCKS) * 128;
        for (int idx = t; idx < 128 * 64; idx += 512) {
            int r = idx >> 6, kc = idx & 63;
            int pt = base + r;
            float v = (pt < N1C) ? feats1[(size_t)pt * 64 + kc] : 0.f;
            __half h = __float2half_rn(v);
            Xhi[r][kc] = h;
            Xlo[r][kc] = __float2half_rn(v - __half2float(h));
        }
        __syncthreads();

        const int w = t >> 5, l = t & 31;
        const int wr = (w >> 1) * 16;
        const int jb = (w & 1) * 2;         // 2 ntiles of 8 cols
        const int gr = l >> 2, c0 = 2 * (l & 3);

        float D[2][4];
#pragma unroll
        for (int j = 0; j < 2; j++) {
            float2 bb = *(const float2*)(bq + (jb + j) * 8 + c0);
            D[j][0] = bb.x; D[j][1] = bb.y; D[j][2] = bb.x; D[j][3] = bb.y;
        }

#pragma unroll
        for (int k = 0; k < 4; k++) {
            const int ka = k * 16 + c0;
            unsigned ah0 = *(const unsigned*)&Xhi[wr + gr][ka];
            unsigned ah1 = *(const unsigned*)&Xhi[wr + gr + 8][ka];
            unsigned ah2 = *(const unsigned*)&Xhi[wr + gr][ka + 8];
            unsigned ah3 = *(const unsigned*)&Xhi[wr + gr + 8][ka + 8];
            unsigned al0 = *(const unsigned*)&Xlo[wr + gr][ka];
            unsigned al1 = *(const unsigned*)&Xlo[wr + gr + 8][ka];
            unsigned al2 = *(const unsigned*)&Xlo[wr + gr][ka + 8];
            unsigned al3 = *(const unsigned*)&Xlo[wr + gr + 8][ka + 8];
#pragma unroll
            for (int j = 0; j < 2; j++) {
                int n = jb + j;
                const uint2 bh = *(const uint2*)&g_fragB_q[((k * 4 + n) * 2 + 0) * 64 + l * 2];
                const uint2 bl = *(const uint2*)&g_fragB_q[((k * 4 + n) * 2 + 1) * 64 + l * 2];
                MMA16816(D[j], ah0, ah1, ah2, ah3, bh.x, bh.y);
                MMA16816(D[j], ah0, ah1, ah2, ah3, bl.x, bl.y);
                MMA16816(D[j], al0, al1, al2, al3, bh.x, bh.y);
            }
        }

        const int r0 = base + wr + gr;
        const int r1 = r0 + 8;
#pragma unroll
        for (int j = 0; j < 2; j++) {
            int colg = (jb + j) * 8 + c0;
            if (r0 < N1C)
                *(float2*)(g_Q + (size_t)r0 * 32 + colg) = make_float2(D[j][0], D[j][1]);
            if (r1 < N1C)
                *(float2*)(g_Q + (size_t)r1 * 32 + colg) = make_float2(D[j][2], D[j][3]);
        }
    } else {
        // ------------- knn_idxs passthrough (int -> float) -------------
        int b = blockIdx.x - KV_BLOCKS - Q_BLOCKS;
        int stride = (gridDim.x - KV_BLOCKS - Q_BLOCKS) * 512;
        for (int i = b * 512 + t; i < tailN; i += stride)
            outTail[i] = (float)knn[i];
    }
}

// ---------------------------------------------------------------------------
// Attention: one warp per query, 8 queries per 256-thread block. (Unchanged.)
// ---------------------------------------------------------------------------
__global__ __launch_bounds__(256) void attn_kernel(
    const float* __restrict__ coords1,
    const int*   __restrict__ knn,
    const float* __restrict__ Wv,
    float*       __restrict__ out)
{
    const int l = threadIdx.x & 31;
    const int n = blockIdx.x * 8 + (threadIdx.x >> 5);

    int myidx = 0;
    if (l < 16) myidx = knn[(size_t)n * 16 + l];

    const int h    = l & 3;
    const int rsub = l >> 2;

    const float4 q0 = *(const float4*)(g_Q + (size_t)n * 32 + h * 8);
    const float4 q1 = *(const float4*)(g_Q + (size_t)n * 32 + h * 8 + 4);

    const int j0 = __shfl_sync(0xffffffffu, myidx, rsub);
    const int j1 = __shfl_sync(0xffffffffu, myidx, 8 + rsub);

    const uint4 kc0 = *(const uint4*)(g_KVh + (size_t)j0 * 128 + h * 8);
    const uint4 kc1 = *(const uint4*)(g_KVh + (size_t)j1 * 128 + h * 8);

    float logit0, logit1;
    {
        const __half2* kh = (const __half2*)&kc0;
        float2 a = __half22float2(kh[0]), b = __half22float2(kh[1]);
        float2 c = __half22float2(kh[2]), d = __half22float2(kh[3]);
        logit0 = a.x * q0.x + a.y * q0.y + b.x * q0.z + b.y * q0.w
               + c.x * q1.x + c.y * q1.y + d.x * q1.z + d.y * q1.w;
    }
    {
        const __half2* kh = (const __half2*)&kc1;
        float2 a = __half22float2(kh[0]), b = __half22float2(kh[1]);
        float2 c = __half22float2(kh[2]), d = __half22float2(kh[3]);
        logit1 = a.x * q0.x + a.y * q0.y + b.x * q0.z + b.y * q0.w
               + c.x * q1.x + c.y * q1.y + d.x * q1.z + d.y * q1.w;
    }
    logit0 *= 0.35355339059327373f;
    logit1 *= 0.35355339059327373f;

    float m = fmaxf(logit0, logit1);
    m = fmaxf(m, __shfl_xor_sync(0xffffffffu, m, 4));
    m = fmaxf(m, __shfl_xor_sync(0xffffffffu, m, 8));
    m = fmaxf(m, __shfl_xor_sync(0xffffffffu, m, 16));
    float e0 = __expf(logit0 - m);
    float e1 = __expf(logit1 - m);
    float s = e0 + e1;
    s += __shfl_xor_sync(0xffffffffu, s, 4);
    s += __shfl_xor_sync(0xffffffffu, s, 8);
    s += __shfl_xor_sync(0xffffffffu, s, 16);
    const float inv_s = __frcp_rn(s);
    const float a0 = e0 * inv_s;
    const float a1 = e1 * inv_s;

    const int hd = l >> 3;
    float accx = 0.0f, accy = 0.0f;
#pragma unroll
    for (int r = 0; r < 16; r++) {
        const int jr = __shfl_sync(0xffffffffu, myidx, r);
        const int src = ((r & 7) << 2) + hd;
        const float ar = __shfl_sync(0xffffffffu, (r < 8) ? a0 : a1, src);
        const __half2 v = *(const __half2*)(g_KVh + (size_t)jr * 128 + 64 + 2 * l);
        const float2 vf = __half22float2(v);
        accx = fmaf(ar, vf.x, accx);
        accy = fmaf(ar, vf.y, accy);
    }

    const float c1x = coords1[(size_t)n * 3 + 0];
    const float c1y = coords1[(size_t)n * 3 + 1];
    const float c1z = coords1[(size_t)n * 3 + 2];
    const float2 wv0 = *(const float2*)(Wv + (size_t)64 * 64 + 2 * l);
    const float2 wv1 = *(const float2*)(Wv + (size_t)65 * 64 + 2 * l);
    const float2 wv2 = *(const float2*)(Wv + (size_t)66 * 64 + 2 * l);
    const float cvx = c1x * wv0.x + c1y * wv1.x + c1z * wv2.x;
    const float cvy = c1x * wv0.y + c1y * wv1.y + c1z * wv2.y;

    *(float2*)(out + (size_t)n * 64 + 2 * l) = make_float2(accx - cvx, accy - cvy);
}

extern "C" void kernel_launch(void* const* d_in, const int* in_sizes, int n_in,
                              void* d_out, int out_size)
{
    const float* coords0 = (const float*)d_in[0];
    const float* coords1 = (const float*)d_in[1];
    const float* feats0  = (const float*)d_in[2];
    const float* feats1  = (const float*)d_in[3];
    const int*   knn     = (const int*)  d_in[4];
    const float* Wq      = (const float*)d_in[5];
    const float* bq      = (const float*)d_in[6];
    const float* Wk      = (const float*)d_in[7];
    const float* bk      = (const float*)d_in[8];
    const float* Wv      = (const float*)d_in[9];
    const float* bv      = (const float*)d_in[10];
    float* out = (float*)d_out;

    int tail = out_size - N1C * 64;
    if (tail < 0) tail = 0;
    int copyBlocks = tail > 0 ? (tail + 2047) / 2048 : 0;

    prepw_kernel<<<1, 512>>>(Wk, Wv, Wq);

    prep_kernel<<<KV_BLOCKS + Q_BLOCKS + copyBlocks, 512>>>(
        feats0, coords0, bk, bv, feats1, bq,
        knn, out + (size_t)N1C * 64, tail);

    attn_kernel<<<N1C / 8, 256>>>(coords1, knn, Wv, out);
}

// round 13
// speedup vs baseline: 1.5453x; 1.1326x over previous
#include <cuda_runtime.h>
#include <cuda_fp16.h>

#define N0C 100000
#define N1C 100000

#define KV_BLOCKS ((N0C + 255) / 256)   // 391
#define Q_BLOCKS  ((N1C + 255) / 256)   // 391

// Packed-f32x2 helpers (Blackwell FFMA2 path, PTX-only)
#define FFMA2(d, a, b, c) \
    asm("fma.rn.f32x2 %0, %1, %2, %3;" : "=l"(d) : "l"(a), "l"(b), "l"(c))
__device__ __forceinline__ unsigned long long pack2(float lo, float hi) {
    unsigned long long r;
    asm("mov.b64 %0, {%1, %2};" : "=l"(r) : "f"(lo), "f"(hi));
    return r;
}
__device__ __forceinline__ float2 unpack2(unsigned long long v) {
    float2 r;
    asm("mov.b64 {%0, %1}, %2;" : "=f"(r.x), "=f"(r.y) : "l"(v));
    return r;
}

// KV0 in fp16, padded rows of 128 halves (256B, line-aligned):
//   halves [0,32)   : K part  (feats0@Wk[0:64] + coords0@Wk[64:67] + bk)
//   halves [64,128) : V part  (feats0@Wv[0:64] + coords0@Wv[64:67] + bv)
__device__ __half g_KVh[(size_t)N0C * 128];
__device__ float  g_Q[(size_t)N1C * 32];

// ---------------------------------------------------------------------------
// Fused prep kernel. Blocks [0,391): KV GEMM (256 rows each, 4 sub-tiles);
// blocks [391,782): Q GEMM (256 rows each); rest: idx passthrough.
// ---------------------------------------------------------------------------
__global__ __launch_bounds__(256) void prep_kernel(
    const float* __restrict__ feats0, const float* __restrict__ coords0,
    const float* __restrict__ Wk, const float* __restrict__ bk,
    const float* __restrict__ Wv, const float* __restrict__ bv,
    const float* __restrict__ feats1,
    const float* __restrict__ Wq, const float* __restrict__ bq,
    const int*   __restrict__ knn, float* __restrict__ outTail, int tailN)
{
    // KV path needs Ws(67*96) + Bs(96) + Xs(67*68): Xs rows are indexed by the
    // 67 input dims (i), NOT the 64 points. 11084 floats = 44.3 KB.
    __shared__ __align__(16) float smem[67 * 96 + 96 + 67 * 68];
    const int t = threadIdx.x;

    if (blockIdx.x < KV_BLOCKS) {
        // ---------------- KV0: [256 pts, 67 in] x [67, 96 out] ----------------
        float (*Ws)[96] = (float (*)[96])smem;                   // weights [i][c]
        float* Bs       = smem + 67 * 96;                        // bias [96]
        float (*Xs)[68] = (float (*)[68])(smem + 67 * 96 + 96);  // inputs [i][p], i<67

        // Stage weights ONCE per 256 rows (float4).
        const float4* Wk4 = (const float4*)Wk;   // 67 x 8
        const float4* Wv4 = (const float4*)Wv;   // 67 x 16
        for (int idx = t; idx < 67 * 24; idx += 256) {
            int i = idx / 24, c4 = idx % 24;
            float4 v = (c4 < 8) ? Wk4[i * 8 + c4] : Wv4[i * 16 + (c4 - 8)];
            *(float4*)&Ws[i][c4 * 4] = v;
        }
        if (t < 96) Bs[t] = (t < 32) ? bk[t] : bv[t - 32];

        const int tc = t & 15;
        const int tp = t >> 4;
        const int c0 = tc * 6;          // even
        const int p0 = tp * 4;
        const int base0 = blockIdx.x * 256;

#pragma unroll 1
        for (int sub = 0; sub < 4; sub++) {
            const int base = base0 + sub * 64;

            // Stage X transposed [i][p] (i fastest in gmem -> coalesced).
            for (int idx = t; idx < 64 * 67; idx += 256) {
                int p = idx / 67, i = idx % 67;
                int pt = base + p;
                float v = 0.0f;
                if (pt < N0C)
                    v = (i < 64) ? feats0[(size_t)pt * 64 + i]
                                 : coords0[(size_t)pt * 3 + (i - 64)];
                Xs[i][p] = v;
            }
            __syncthreads();

            unsigned long long acc2[4][3];
#pragma unroll
            for (int m = 0; m < 3; m++) {
                unsigned long long b = pack2(Bs[c0 + 2 * m], Bs[c0 + 2 * m + 1]);
#pragma unroll
                for (int pp = 0; pp < 4; pp++) acc2[pp][m] = b;
            }

#pragma unroll 4
            for (int i = 0; i < 67; i++) {
                const float4 xv = *(const float4*)&Xs[i][p0];
                const unsigned long long* wrow = (const unsigned long long*)&Ws[i][c0];
                const unsigned long long w0 = wrow[0], w1 = wrow[1], w2 = wrow[2];
                unsigned long long xx[4];
                xx[0] = pack2(xv.x, xv.x); xx[1] = pack2(xv.y, xv.y);
                xx[2] = pack2(xv.z, xv.z); xx[3] = pack2(xv.w, xv.w);
#pragma unroll
                for (int pp = 0; pp < 4; pp++) {
                    FFMA2(acc2[pp][0], xx[pp], w0, acc2[pp][0]);
                    FFMA2(acc2[pp][1], xx[pp], w1, acc2[pp][1]);
                    FFMA2(acc2[pp][2], xx[pp], w2, acc2[pp][2]);
                }
            }

#pragma unroll
            for (int pp = 0; pp < 4; pp++) {
                int pt = base + p0 + pp;
                if (pt < N0C) {
                    __half* row = g_KVh + (size_t)pt * 128;
#pragma unroll
                    for (int m = 0; m < 3; m++) {
                        int c = c0 + 2 * m;                 // pair never straddles c=32
                        int hidx = (c < 32) ? c : c + 32;   // V shifted to half-idx 64+
                        float2 v = unpack2(acc2[pp][m]);
                        *(__half2*)(row + hidx) = __floats2half2_rn(v.x, v.y);
                    }
                }
            }
            __syncthreads();
        }
    } else if (blockIdx.x < KV_BLOCKS + Q_BLOCKS) {
        // ---------------- Q: [256 pts, 64 in] x [64, 32 out] ----------------
        float (*Ws)[32] = (float (*)[32])smem;                   // [64][32]
        float* Bs       = smem + 64 * 32;                        // [32]
        float (*Xs)[68] = (float (*)[68])(smem + 64 * 32 + 32);  // [i][p], i<64

        // Flat float4 copy of the 64x32 weight tile.
        const float4* Wq4 = (const float4*)Wq;
        for (int idx = t; idx < 512; idx += 256)
            ((float4*)Ws)[idx] = Wq4[idx];
        if (t < 32) Bs[t] = bq[t];

        const int tc = t & 15;
        const int tp = t >> 4;
        const int c0 = tc * 2;          // even
        const int p0 = tp * 4;
        const int base0 = (blockIdx.x - KV_BLOCKS) * 256;

#pragma unroll 1
        for (int sub = 0; sub < 4; sub++) {
            const int base = base0 + sub * 64;

            for (int idx = t; idx < 64 * 64; idx += 256) {
                int p = idx >> 6, i = idx & 63;
                int pt = base + p;
                Xs[i][p] = (pt < N1C) ? feats1[(size_t)pt * 64 + i] : 0.0f;
            }
            __syncthreads();

            unsigned long long acc2[4];
            {
                unsigned long long b = pack2(Bs[c0], Bs[c0 + 1]);
#pragma unroll
                for (int pp = 0; pp < 4; pp++) acc2[pp] = b;
            }

#pragma unroll 8
            for (int i = 0; i < 64; i++) {
                const float4 xv = *(const float4*)&Xs[i][p0];
                const unsigned long long w = *(const unsigned long long*)&Ws[i][c0];
                unsigned long long xx[4];
                xx[0] = pack2(xv.x, xv.x); xx[1] = pack2(xv.y, xv.y);
                xx[2] = pack2(xv.z, xv.z); xx[3] = pack2(xv.w, xv.w);
#pragma unroll
                for (int pp = 0; pp < 4; pp++)
                    FFMA2(acc2[pp], xx[pp], w, acc2[pp]);
            }

#pragma unroll
            for (int pp = 0; pp < 4; pp++) {
                int pt = base + p0 + pp;
                if (pt < N1C) {
                    float2 v = unpack2(acc2[pp]);
                    *(float2*)(g_Q + (size_t)pt * 32 + c0) = v;
                }
            }
            __syncthreads();
        }
    } else {
        // ---------------- knn_idxs passthrough (int -> float) ----------------
        int b = blockIdx.x - KV_BLOCKS - Q_BLOCKS;
        int stride = (gridDim.x - KV_BLOCKS - Q_BLOCKS) * 256;
        for (int i = b * 256 + t; i < tailN; i += stride)
            outTail[i] = (float)knn[i];
    }
}

// ---------------------------------------------------------------------------
// Attention: ONE warp per query, 8 queries per 256-thread block. (Unchanged:
// 39.4us, MIO/L1-wavefront bound at ~its floor for this layout.)
// ---------------------------------------------------------------------------
__global__ __launch_bounds__(256) void attn_kernel(
    const float* __restrict__ coords1,
    const int*   __restrict__ knn,
    const float* __restrict__ Wv,
    float*       __restrict__ out)
{
    const int l = threadIdx.x & 31;
    const int n = blockIdx.x * 8 + (threadIdx.x >> 5);  // N1C % 8 == 0

    int myidx = 0;
    if (l < 16) myidx = knn[(size_t)n * 16 + l];

    const int h    = l & 3;        // head for phase A
    const int rsub = l >> 2;       // row sub-index (0..7)

    const float4 q0 = *(const float4*)(g_Q + (size_t)n * 32 + h * 8);
    const float4 q1 = *(const float4*)(g_Q + (size_t)n * 32 + h * 8 + 4);

    const int j0 = __shfl_sync(0xffffffffu, myidx, rsub);
    const int j1 = __shfl_sync(0xffffffffu, myidx, 8 + rsub);

    const uint4 kc0 = *(const uint4*)(g_KVh + (size_t)j0 * 128 + h * 8);
    const uint4 kc1 = *(const uint4*)(g_KVh + (size_t)j1 * 128 + h * 8);

    float logit0, logit1;
    {
        const __half2* kh = (const __half2*)&kc0;
        float2 a = __half22float2(kh[0]), b = __half22float2(kh[1]);
        float2 c = __half22float2(kh[2]), d = __half22float2(kh[3]);
        logit0 = a.x * q0.x + a.y * q0.y + b.x * q0.z + b.y * q0.w
               + c.x * q1.x + c.y * q1.y + d.x * q1.z + d.y * q1.w;
    }
    {
        const __half2* kh = (const __half2*)&kc1;
        float2 a = __half22float2(kh[0]), b = __half22float2(kh[1]);
        float2 c = __half22float2(kh[2]), d = __half22float2(kh[3]);
        logit1 = a.x * q0.x + a.y * q0.y + b.x * q0.z + b.y * q0.w
               + c.x * q1.x + c.y * q1.y + d.x * q1.z + d.y * q1.w;
    }
    logit0 *= 0.35355339059327373f;
    logit1 *= 0.35355339059327373f;

    // softmax across 16 rows of this head: lanes {h, h+4, ..., h+28} x 2 regs
    float m = fmaxf(logit0, logit1);
    m = fmaxf(m, __shfl_xor_sync(0xffffffffu, m, 4));
    m = fmaxf(m, __shfl_xor_sync(0xffffffffu, m, 8));
    m = fmaxf(m, __shfl_xor_sync(0xffffffffu, m, 16));
    float e0 = __expf(logit0 - m);
    float e1 = __expf(logit1 - m);
    float s = e0 + e1;
    s += __shfl_xor_sync(0xffffffffu, s, 4);
    s += __shfl_xor_sync(0xffffffffu, s, 8);
    s += __shfl_xor_sync(0xffffffffu, s, 16);
    const float inv_s = __frcp_rn(s);
    const float a0 = e0 * inv_s;
    const float a1 = e1 * inv_s;

    // Phase B: lane owns output dims (2l, 2l+1); head of those dims = l>>3.
    const int hd = l >> 3;
    float accx = 0.0f, accy = 0.0f;
#pragma unroll
    for (int r = 0; r < 16; r++) {
        const int jr = __shfl_sync(0xffffffffu, myidx, r);
        const int src = ((r & 7) << 2) + hd;
        const float ar = __shfl_sync(0xffffffffu, (r < 8) ? a0 : a1, src);
        const __half2 v = *(const __half2*)(g_KVh + (size_t)jr * 128 + 64 + 2 * l);
        const float2 vf = __half22float2(v);
        accx = fmaf(ar, vf.x, accx);
        accy = fmaf(ar, vf.y, accy);
    }

    const float c1x = coords1[(size_t)n * 3 + 0];
    const float c1y = coords1[(size_t)n * 3 + 1];
    const float c1z = coords1[(size_t)n * 3 + 2];
    const float2 wv0 = *(const float2*)(Wv + (size_t)64 * 64 + 2 * l);
    const float2 wv1 = *(const float2*)(Wv + (size_t)65 * 64 + 2 * l);
    const float2 wv2 = *(const float2*)(Wv + (size_t)66 * 64 + 2 * l);
    const float cvx = c1x * wv0.x + c1y * wv1.x + c1z * wv2.x;
    const float cvy = c1x * wv0.y + c1y * wv1.y + c1z * wv2.y;

    *(float2*)(out + (size_t)n * 64 + 2 * l) = make_float2(accx - cvx, accy - cvy);
}

extern "C" void kernel_launch(void* const* d_in, const int* in_sizes, int n_in,
                              void* d_out, int out_size)
{
    const float* coords0 = (const float*)d_in[0];
    const float* coords1 = (const float*)d_in[1];
    const float* feats0  = (const float*)d_in[2];
    const float* feats1  = (const float*)d_in[3];
    const int*   knn     = (const int*)  d_in[4];
    const float* Wq      = (const float*)d_in[5];
    const float* bq      = (const float*)d_in[6];
    const float* Wk      = (const float*)d_in[7];
    const float* bk      = (const float*)d_in[8];
    const float* Wv      = (const float*)d_in[9];
    const float* bv      = (const float*)d_in[10];
    float* out = (float*)d_out;

    int tail = out_size - N1C * 64;
    if (tail < 0) tail = 0;
    int copyBlocks = tail > 0 ? (tail + 1023) / 1024 : 0;

    prep_kernel<<<KV_BLOCKS + Q_BLOCKS + copyBlocks, 256>>>(
        feats0, coords0, Wk, bk, Wv, bv,
        feats1, Wq, bq,
        knn, out + (size_t)N1C * 64, tail);

    attn_kernel<<<N1C / 8, 256>>>(coords1, knn, Wv, out);
}